// round 2
// baseline (speedup 1.0000x reference)
#include <cuda_runtime.h>

// ---------------- problem constants ----------------
constexpr int B    = 16;
constexpr int CIN  = 4;
constexpr int D0   = 64;
constexpr int D1   = 34;   // conv1 output spatial
constexpr int D2   = 19;   // conv2 output spatial
constexpr int KS   = 7;
constexpr int TAPS = KS * KS * KS;      // 343
constexpr int C1   = 24;   // conv1 out channels (8 vectors x 3)
constexpr int NG   = 8;    // vector multiplicity
constexpr int F2   = 72;   // folded conv2 in features: 24 + 8*6
constexpr int C2   = 16;   // conv2 out channels
constexpr long VOX1 = (long)D1 * D1 * D1;   // 39304
constexpr long VOX2 = (long)D2 * D2 * D2;   // 6859

// ---------------- scratch ----------------
__device__ float g_K1[CIN * TAPS * C1];          // [cin][tap][co]
__device__ float g_K2[F2 * TAPS * C2];           // [cin][tap][co]
__device__ float g_vt[(long)B * F2 * VOX1];      // features for conv2
__device__ float g_stats_acc[2 * C2];            // sum, sumsq accumulators
__device__ float g_stats[2 * C2];                // mean, rstd

// ---------------- build equivariant kernels ----------------
__global__ void build_kernels(const float* __restrict__ basis1,
                              const float* __restrict__ W1,
                              const float* __restrict__ basis2a,
                              const float* __restrict__ basis2b,
                              const float* __restrict__ W2a,
                              const float* __restrict__ W2b) {
    int id = blockIdx.x * blockDim.x + threadIdx.x;
    const int N1 = CIN * TAPS * C1;
    const int N2 = F2 * TAPS * C2;
    // also zero the stats accumulators
    if (id < 2 * C2) g_stats_acc[id] = 0.f;
    if (id < N1) {
        int co = id % C1;
        int t  = (id / C1) % TAPS;
        int ci = id / (C1 * TAPS);
        int u = co / 3, i = co % 3;
        float acc = 0.f;
#pragma unroll
        for (int b = 0; b < 3; b++)
            acc += W1[(u * CIN + ci) * 3 + b] * basis1[(b * 3 + i) * TAPS + t];
        g_K1[id] = acc;
    } else if (id < N1 + N2) {
        int id2 = id - N1;
        int co = id2 % C2;
        int t  = (id2 / C2) % TAPS;
        int ci = id2 / (C2 * TAPS);
        float acc = 0.f;
        if (ci < 24) {
            int v = ci / 3, j = ci % 3;
#pragma unroll
            for (int b = 0; b < 3; b++)
                acc += W2a[(co * NG + v) * 3 + b] * basis2a[(b * 3 + j) * TAPS + t];
        } else {
            int c = ci - 24;
            int g = c / 6, p = c % 6;
            const int PI[6] = {0, 0, 0, 1, 1, 2};
            const int PJ[6] = {0, 1, 2, 1, 2, 2};
            int i = PI[p], j = PJ[p];
#pragma unroll
            for (int b = 0; b < 3; b++) {
                float bb = basis2b[(b * 9 + i * 3 + j) * TAPS + t];
                if (i != j) bb += basis2b[(b * 9 + j * 3 + i) * TAPS + t];
                acc += W2b[(co * NG + g) * 3 + b] * bb;
            }
        }
        g_K2[id2] = acc;
    }
}

// ---------------- conv1: s[16,4,64^3] -> vt[:, 0:24, 34^3] ----------------
__global__ __launch_bounds__(256) void conv1_kernel(const float* __restrict__ s) {
    __shared__ float ws[TAPS * C1];   // one cin slice: 32928 B
    long gid = (long)blockIdx.x * blockDim.x + threadIdx.x;
    bool active = gid < (long)B * VOX1;
    int b = 0, oz = 0, oy = 0, ox = 0;
    long r = 0;
    if (active) {
        b = (int)(gid / VOX1);
        r = gid % VOX1;
        oz = (int)(r / (D1 * D1));
        int rr = (int)(r % (D1 * D1));
        oy = rr / D1;
        ox = rr % D1;
    }
    float acc[C1];
#pragma unroll
    for (int c = 0; c < C1; c++) acc[c] = 0.f;

    int izb = oz * 2 - 5, iyb = oy * 2 - 5, ixb = ox * 2 - 5;

    for (int ci = 0; ci < CIN; ci++) {
        __syncthreads();
        for (int i = threadIdx.x; i < TAPS * C1; i += blockDim.x)
            ws[i] = g_K1[ci * TAPS * C1 + i];
        __syncthreads();
        if (!active) continue;
        const float* sb = s + ((long)(b * CIN + ci)) * D0 * D0 * D0;
        for (int kz = 0; kz < KS; kz++) {
            int iz = izb + kz;
            if ((unsigned)iz >= (unsigned)D0) continue;
            for (int ky = 0; ky < KS; ky++) {
                int iy = iyb + ky;
                if ((unsigned)iy >= (unsigned)D0) continue;
                const float* srow = sb + ((long)iz * D0 + iy) * D0 + ixb;
                const float* wrow = ws + (kz * KS + ky) * KS * C1;
#pragma unroll
                for (int kx = 0; kx < KS; kx++) {
                    int ix = ixb + kx;
                    float val = ((unsigned)ix < (unsigned)D0) ? __ldg(srow + kx) : 0.f;
                    const float* w = wrow + kx * C1;
#pragma unroll
                    for (int c = 0; c < C1; c++) acc[c] = fmaf(val, w[c], acc[c]);
                }
            }
        }
    }
    if (active) {
        float* dst = g_vt + (long)b * F2 * VOX1 + r;
#pragma unroll
        for (int c = 0; c < C1; c++) dst[(long)c * VOX1] = acc[c];
    }
}

// ---------------- tensor product: fill folded features 24..71 ----------------
__global__ void tprod_kernel() {
    long gid = (long)blockIdx.x * blockDim.x + threadIdx.x;
    long total = (long)B * NG * VOX1;
    if (gid >= total) return;
    long r = gid % VOX1;
    int gg = (int)((gid / VOX1) % NG);
    int b  = (int)(gid / (VOX1 * NG));
    float* base = g_vt + (long)b * F2 * VOX1;
    float v0 = base[(long)(3 * gg + 0) * VOX1 + r];
    float v1 = base[(long)(3 * gg + 1) * VOX1 + r];
    float v2 = base[(long)(3 * gg + 2) * VOX1 + r];
    float* dst = base + (long)(24 + gg * 6) * VOX1 + r;
    dst[0 * VOX1] = v0 * v0;
    dst[1 * VOX1] = v0 * v1;
    dst[2 * VOX1] = v0 * v2;
    dst[3 * VOX1] = v1 * v1;
    dst[4 * VOX1] = v1 * v2;
    dst[5 * VOX1] = v2 * v2;
}

// ---------------- conv2: vt[16,72,34^3] -> y[16,16,19^3] ----------------
__global__ __launch_bounds__(256) void conv2_kernel(float* __restrict__ y) {
    __shared__ float ws[TAPS * C2];   // one cin slice: 21952 B
    long gid = (long)blockIdx.x * blockDim.x + threadIdx.x;
    bool active = gid < (long)B * VOX2;
    int b = 0, oz = 0, oy = 0, ox = 0;
    long r = 0;
    if (active) {
        b = (int)(gid / VOX2);
        r = gid % VOX2;
        oz = (int)(r / (D2 * D2));
        int rr = (int)(r % (D2 * D2));
        oy = rr / D2;
        ox = rr % D2;
    }
    float acc[C2];
#pragma unroll
    for (int c = 0; c < C2; c++) acc[c] = 0.f;

    int izb = oz * 2 - 5, iyb = oy * 2 - 5, ixb = ox * 2 - 5;

    for (int ci = 0; ci < F2; ci++) {
        __syncthreads();
        for (int i = threadIdx.x; i < TAPS * C2; i += blockDim.x)
            ws[i] = g_K2[ci * TAPS * C2 + i];
        __syncthreads();
        if (!active) continue;
        const float* fb = g_vt + ((long)b * F2 + ci) * VOX1;
        for (int kz = 0; kz < KS; kz++) {
            int iz = izb + kz;
            if ((unsigned)iz >= (unsigned)D1) continue;
            for (int ky = 0; ky < KS; ky++) {
                int iy = iyb + ky;
                if ((unsigned)iy >= (unsigned)D1) continue;
                const float* frow = fb + ((long)iz * D1 + iy) * D1 + ixb;
                const float* wrow = ws + (kz * KS + ky) * KS * C2;
#pragma unroll
                for (int kx = 0; kx < KS; kx++) {
                    int ix = ixb + kx;
                    float val = ((unsigned)ix < (unsigned)D1) ? __ldg(frow + kx) : 0.f;
                    const float* w = wrow + kx * C2;
#pragma unroll
                    for (int c = 0; c < C2; c++) acc[c] = fmaf(val, w[c], acc[c]);
                }
            }
        }
    }
    if (active) {
        float* dst = y + (long)b * C2 * VOX2 + r;
#pragma unroll
        for (int c = 0; c < C2; c++) dst[(long)c * VOX2] = acc[c];
    }
}

// ---------------- batch-norm stats: 4 blocks per channel, atomic combine ----
__global__ void stats_partial_kernel(const float* __restrict__ y) {
    __shared__ float ssum[256], ssq[256];
    int co   = blockIdx.x & (C2 - 1);
    int part = blockIdx.x / C2;      // 0..3
    int tid  = threadIdx.x;
    float s = 0.f, q = 0.f;
    long n = (long)B * VOX2;
    for (long i = part * 256 + tid; i < n; i += 4 * 256) {
        int b  = (int)(i / VOX2);
        long r = i % VOX2;
        float v = y[((long)b * C2 + co) * VOX2 + r];
        s += v;
        q += v * v;
    }
    ssum[tid] = s; ssq[tid] = q;
    __syncthreads();
    for (int st = 128; st > 0; st >>= 1) {
        if (tid < st) { ssum[tid] += ssum[tid + st]; ssq[tid] += ssq[tid + st]; }
        __syncthreads();
    }
    if (tid == 0) {
        atomicAdd(&g_stats_acc[co], ssum[0]);
        atomicAdd(&g_stats_acc[C2 + co], ssq[0]);
    }
}

__global__ void stats_final_kernel() {
    int co = threadIdx.x;
    if (co >= C2) return;
    float fn = (float)((long)B * VOX2);
    float mean = g_stats_acc[co] / fn;
    float var  = g_stats_acc[C2 + co] / fn - mean * mean;
    g_stats[co]      = mean;
    g_stats[C2 + co] = rsqrtf(var + 1e-5f);
}

// ---------------- normalize + bias + relu (in place) ----------------
__global__ void finalize_kernel(float* __restrict__ y,
                                const float* __restrict__ gamma,
                                const float* __restrict__ beta,
                                const float* __restrict__ bias) {
    long gid = (long)blockIdx.x * blockDim.x + threadIdx.x;
    long total = (long)B * C2 * VOX2;
    if (gid >= total) return;
    int co = (int)((gid / VOX2) % C2);
    float v = y[gid];
    v = (v - g_stats[co]) * g_stats[C2 + co] * gamma[co] + beta[co] + bias[co];
    y[gid] = v > 0.f ? v : 0.f;
}

// ---------------- launch ----------------
extern "C" void kernel_launch(void* const* d_in, const int* in_sizes, int n_in,
                              void* d_out, int out_size) {
    const float* s       = (const float*)d_in[0];
    const float* basis1  = (const float*)d_in[1];
    const float* W1      = (const float*)d_in[2];
    const float* basis2a = (const float*)d_in[3];
    const float* basis2b = (const float*)d_in[4];
    const float* W2a     = (const float*)d_in[5];
    const float* W2b     = (const float*)d_in[6];
    const float* gamma   = (const float*)d_in[7];
    const float* beta    = (const float*)d_in[8];
    const float* bias    = (const float*)d_in[9];
    float* y = (float*)d_out;

    const int T = 256;
    int nBuild = (CIN * TAPS * C1 + F2 * TAPS * C2 + T - 1) / T;
    build_kernels<<<nBuild, T>>>(basis1, W1, basis2a, basis2b, W2a, W2b);

    long n1 = (long)B * VOX1;
    conv1_kernel<<<(int)((n1 + T - 1) / T), T>>>(s);

    long nt = (long)B * NG * VOX1;
    tprod_kernel<<<(int)((nt + T - 1) / T), T>>>();

    long n2 = (long)B * VOX2;
    conv2_kernel<<<(int)((n2 + T - 1) / T), T>>>(y);

    stats_partial_kernel<<<4 * C2, 256>>>(y);
    stats_final_kernel<<<1, 32>>>();

    long nf = (long)B * C2 * VOX2;
    finalize_kernel<<<(int)((nf + T - 1) / T), T>>>(y, gamma, beta, bias);
}

// round 3
// speedup vs baseline: 1.1108x; 1.1108x over previous
#include <cuda_runtime.h>

// ---------------- problem constants ----------------
constexpr int B    = 16;
constexpr int CIN  = 4;
constexpr int D0   = 64;
constexpr int D1   = 34;   // conv1 output spatial
constexpr int D2   = 19;   // conv2 output spatial
constexpr int KS   = 7;
constexpr int TAPS = KS * KS * KS;      // 343
constexpr int C1   = 24;   // conv1 out channels (8 vectors x 3)
constexpr int NG   = 8;    // vector multiplicity
constexpr int F2   = 72;   // folded conv2 in features: 24 + 8*6
constexpr int C2   = 16;   // conv2 out channels
constexpr long VOX1 = (long)D1 * D1 * D1;   // 39304
constexpr long VOX2 = (long)D2 * D2 * D2;   // 6859
constexpr int GX1  = D1 / 2;                // 17 x-groups (exact)
constexpr int GX2  = (D2 + 1) / 2;          // 10 x-groups (last half)

// ---------------- scratch ----------------
__device__ float g_K1[CIN * TAPS * C1];          // [cin][tap][co]
__device__ float g_K2[F2 * TAPS * C2];           // [cin][tap][co]
__device__ float g_vt[(long)B * F2 * VOX1];      // features for conv2
__device__ float g_stats_acc[2 * C2];            // sum, sumsq accumulators
__device__ float g_stats[2 * C2];                // mean, rstd

// ---------------- build equivariant kernels ----------------
__global__ void build_kernels(const float* __restrict__ basis1,
                              const float* __restrict__ W1,
                              const float* __restrict__ basis2a,
                              const float* __restrict__ basis2b,
                              const float* __restrict__ W2a,
                              const float* __restrict__ W2b) {
    int id = blockIdx.x * blockDim.x + threadIdx.x;
    const int N1 = CIN * TAPS * C1;
    const int N2 = F2 * TAPS * C2;
    if (id < 2 * C2) g_stats_acc[id] = 0.f;
    if (id < N1) {
        int co = id % C1;
        int t  = (id / C1) % TAPS;
        int ci = id / (C1 * TAPS);
        int u = co / 3, i = co % 3;
        float acc = 0.f;
#pragma unroll
        for (int b = 0; b < 3; b++)
            acc += W1[(u * CIN + ci) * 3 + b] * basis1[(b * 3 + i) * TAPS + t];
        g_K1[id] = acc;
    } else if (id < N1 + N2) {
        int id2 = id - N1;
        int co = id2 % C2;
        int t  = (id2 / C2) % TAPS;
        int ci = id2 / (C2 * TAPS);
        float acc = 0.f;
        if (ci < 24) {
            int v = ci / 3, j = ci % 3;
#pragma unroll
            for (int b = 0; b < 3; b++)
                acc += W2a[(co * NG + v) * 3 + b] * basis2a[(b * 3 + j) * TAPS + t];
        } else {
            int c = ci - 24;
            int g = c / 6, p = c % 6;
            const int PI[6] = {0, 0, 0, 1, 1, 2};
            const int PJ[6] = {0, 1, 2, 1, 2, 2};
            int i = PI[p], j = PJ[p];
#pragma unroll
            for (int b = 0; b < 3; b++) {
                float bb = basis2b[(b * 9 + i * 3 + j) * TAPS + t];
                if (i != j) bb += basis2b[(b * 9 + j * 3 + i) * TAPS + t];
                acc += W2b[(co * NG + g) * 3 + b] * bb;
            }
        }
        g_K2[id2] = acc;
    }
}

// ---------------- conv1 + fused tensor product ----------------
// 2 output voxels along x per thread; writes all 72 vt features.
__global__ __launch_bounds__(256, 2) void conv1_kernel(const float* __restrict__ s) {
    __shared__ float ws[TAPS * C1];   // one cin slice: 32928 B
    long gid = (long)blockIdx.x * blockDim.x + threadIdx.x;
    const long NOUT = (long)B * D1 * D1 * GX1;
    bool active = gid < NOUT;
    int b = 0, oz = 0, oy = 0, ox0 = 0;
    long rbase = 0;
    if (active) {
        long t = gid;
        int oxg = (int)(t % GX1); t /= GX1;
        oy = (int)(t % D1); t /= D1;
        oz = (int)(t % D1); b = (int)(t / D1);
        ox0 = oxg * 2;
        rbase = ((long)oz * D1 + oy) * D1 + ox0;
    }
    float acc0[C1], acc1[C1];
#pragma unroll
    for (int c = 0; c < C1; c++) { acc0[c] = 0.f; acc1[c] = 0.f; }

    int izb = oz * 2 - 5, iyb = oy * 2 - 5, ixb = ox0 * 2 - 5;

    for (int ci = 0; ci < CIN; ci++) {
        __syncthreads();
        for (int i = threadIdx.x; i < TAPS * C1; i += blockDim.x)
            ws[i] = g_K1[ci * TAPS * C1 + i];
        __syncthreads();
        if (!active) continue;
        const float* sb = s + ((long)(b * CIN + ci)) * D0 * D0 * D0;
        for (int kz = 0; kz < KS; kz++) {
            int iz = izb + kz;
            if ((unsigned)iz >= (unsigned)D0) continue;
            for (int ky = 0; ky < KS; ky++) {
                int iy = iyb + ky;
                if ((unsigned)iy >= (unsigned)D0) continue;
                const float* frow = sb + ((long)iz * D0 + iy) * D0;
                float in[9];
#pragma unroll
                for (int j = 0; j < 9; j++) {
                    int ix = ixb + j;
                    in[j] = ((unsigned)ix < (unsigned)D0) ? __ldg(frow + ix) : 0.f;
                }
                const float* wrow = ws + (kz * KS + ky) * KS * C1;
#pragma unroll
                for (int kx = 0; kx < KS; kx++) {
                    const float* w = wrow + kx * C1;
                    float v0 = in[kx], v1 = in[kx + 2];
#pragma unroll
                    for (int c = 0; c < C1; c++) {
                        acc0[c] = fmaf(v0, w[c], acc0[c]);
                        acc1[c] = fmaf(v1, w[c], acc1[c]);
                    }
                }
            }
        }
    }
    if (active) {
        float* base = g_vt + (long)b * F2 * VOX1 + rbase;
        // vector channels 0..23 (float2: rbase is always even -> 8B aligned)
#pragma unroll
        for (int c = 0; c < C1; c++)
            *reinterpret_cast<float2*>(base + (long)c * VOX1) = make_float2(acc0[c], acc1[c]);
        // folded tensor-product channels 24..71
#pragma unroll
        for (int g = 0; g < NG; g++) {
            float a0 = acc0[3 * g], b0 = acc0[3 * g + 1], c0 = acc0[3 * g + 2];
            float a1 = acc1[3 * g], b1 = acc1[3 * g + 1], c1 = acc1[3 * g + 2];
            float* dst = base + (long)(24 + g * 6) * VOX1;
            *reinterpret_cast<float2*>(dst + 0 * VOX1) = make_float2(a0 * a0, a1 * a1);
            *reinterpret_cast<float2*>(dst + 1 * VOX1) = make_float2(a0 * b0, a1 * b1);
            *reinterpret_cast<float2*>(dst + 2 * VOX1) = make_float2(a0 * c0, a1 * c1);
            *reinterpret_cast<float2*>(dst + 3 * VOX1) = make_float2(b0 * b0, b1 * b1);
            *reinterpret_cast<float2*>(dst + 4 * VOX1) = make_float2(b0 * c0, b1 * c1);
            *reinterpret_cast<float2*>(dst + 5 * VOX1) = make_float2(c0 * c0, c1 * c1);
        }
    }
}

// ---------------- conv2: vt[16,72,34^3] -> y[16,16,19^3], 2 voxels/thread ----
__global__ __launch_bounds__(256, 2) void conv2_kernel(float* __restrict__ y) {
    __shared__ float ws[TAPS * C2];   // one cin slice: 21952 B
    long gid = (long)blockIdx.x * blockDim.x + threadIdx.x;
    const long NOUT = (long)B * D2 * D2 * GX2;
    bool active = gid < NOUT;
    int b = 0, oz = 0, oy = 0, ox0 = 0;
    long rbase = 0;
    if (active) {
        long t = gid;
        int oxg = (int)(t % GX2); t /= GX2;
        oy = (int)(t % D2); t /= D2;
        oz = (int)(t % D2); b = (int)(t / D2);
        ox0 = oxg * 2;
        rbase = ((long)oz * D2 + oy) * D2 + ox0;
    }
    float acc0[C2], acc1[C2];
#pragma unroll
    for (int c = 0; c < C2; c++) { acc0[c] = 0.f; acc1[c] = 0.f; }

    int izb = oz * 2 - 5, iyb = oy * 2 - 5, ixb = ox0 * 2 - 5;

    for (int ci = 0; ci < F2; ci++) {
        __syncthreads();
        for (int i = threadIdx.x; i < TAPS * C2; i += blockDim.x)
            ws[i] = g_K2[ci * TAPS * C2 + i];
        __syncthreads();
        if (!active) continue;
        const float* fb = g_vt + ((long)b * F2 + ci) * VOX1;
        for (int kz = 0; kz < KS; kz++) {
            int iz = izb + kz;
            if ((unsigned)iz >= (unsigned)D1) continue;
            for (int ky = 0; ky < KS; ky++) {
                int iy = iyb + ky;
                if ((unsigned)iy >= (unsigned)D1) continue;
                const float* frow = fb + ((long)iz * D1 + iy) * D1;
                float in[9];
#pragma unroll
                for (int j = 0; j < 9; j++) {
                    int ix = ixb + j;
                    in[j] = ((unsigned)ix < (unsigned)D1) ? __ldg(frow + ix) : 0.f;
                }
                const float* wrow = ws + (kz * KS + ky) * KS * C2;
#pragma unroll
                for (int kx = 0; kx < KS; kx++) {
                    const float* w = wrow + kx * C2;
                    float v0 = in[kx], v1 = in[kx + 2];
#pragma unroll
                    for (int c = 0; c < C2; c++) {
                        acc0[c] = fmaf(v0, w[c], acc0[c]);
                        acc1[c] = fmaf(v1, w[c], acc1[c]);
                    }
                }
            }
        }
    }
    if (active) {
        float* dst = y + (long)b * C2 * VOX2 + rbase;
        bool second = (ox0 + 1) < D2;
#pragma unroll
        for (int c = 0; c < C2; c++) {
            dst[(long)c * VOX2] = acc0[c];
            if (second) dst[(long)c * VOX2 + 1] = acc1[c];
        }
    }
}

// ---------------- batch-norm stats: 4 blocks per channel, atomic combine ----
__global__ void stats_partial_kernel(const float* __restrict__ y) {
    __shared__ float ssum[256], ssq[256];
    int co   = blockIdx.x & (C2 - 1);
    int part = blockIdx.x / C2;      // 0..3
    int tid  = threadIdx.x;
    float s = 0.f, q = 0.f;
    long n = (long)B * VOX2;
    for (long i = part * 256 + tid; i < n; i += 4 * 256) {
        int b  = (int)(i / VOX2);
        long r = i % VOX2;
        float v = y[((long)b * C2 + co) * VOX2 + r];
        s += v;
        q += v * v;
    }
    ssum[tid] = s; ssq[tid] = q;
    __syncthreads();
    for (int st = 128; st > 0; st >>= 1) {
        if (tid < st) { ssum[tid] += ssum[tid + st]; ssq[tid] += ssq[tid + st]; }
        __syncthreads();
    }
    if (tid == 0) {
        atomicAdd(&g_stats_acc[co], ssum[0]);
        atomicAdd(&g_stats_acc[C2 + co], ssq[0]);
    }
}

__global__ void stats_final_kernel() {
    int co = threadIdx.x;
    if (co >= C2) return;
    float fn = (float)((long)B * VOX2);
    float mean = g_stats_acc[co] / fn;
    float var  = g_stats_acc[C2 + co] / fn - mean * mean;
    g_stats[co]      = mean;
    g_stats[C2 + co] = rsqrtf(var + 1e-5f);
}

// ---------------- normalize + bias + relu (in place) ----------------
__global__ void finalize_kernel(float* __restrict__ y,
                                const float* __restrict__ gamma,
                                const float* __restrict__ beta,
                                const float* __restrict__ bias) {
    long gid = (long)blockIdx.x * blockDim.x + threadIdx.x;
    long total = (long)B * C2 * VOX2;
    if (gid >= total) return;
    int co = (int)((gid / VOX2) % C2);
    float v = y[gid];
    v = (v - g_stats[co]) * g_stats[C2 + co] * gamma[co] + beta[co] + bias[co];
    y[gid] = v > 0.f ? v : 0.f;
}

// ---------------- launch ----------------
extern "C" void kernel_launch(void* const* d_in, const int* in_sizes, int n_in,
                              void* d_out, int out_size) {
    const float* s       = (const float*)d_in[0];
    const float* basis1  = (const float*)d_in[1];
    const float* W1      = (const float*)d_in[2];
    const float* basis2a = (const float*)d_in[3];
    const float* basis2b = (const float*)d_in[4];
    const float* W2a     = (const float*)d_in[5];
    const float* W2b     = (const float*)d_in[6];
    const float* gamma   = (const float*)d_in[7];
    const float* beta    = (const float*)d_in[8];
    const float* bias    = (const float*)d_in[9];
    float* y = (float*)d_out;

    const int T = 256;
    int nBuild = (CIN * TAPS * C1 + F2 * TAPS * C2 + T - 1) / T;
    build_kernels<<<nBuild, T>>>(basis1, W1, basis2a, basis2b, W2a, W2b);

    long n1 = (long)B * D1 * D1 * GX1;
    conv1_kernel<<<(int)((n1 + T - 1) / T), T>>>(s);

    long n2 = (long)B * D2 * D2 * GX2;
    conv2_kernel<<<(int)((n2 + T - 1) / T), T>>>(y);

    stats_partial_kernel<<<4 * C2, 256>>>(y);
    stats_final_kernel<<<1, 32>>>();

    long nf = (long)B * C2 * VOX2;
    finalize_kernel<<<(int)((nf + T - 1) / T), T>>>(y, gamma, beta, bias);
}